// round 11
// baseline (speedup 1.0000x reference)
#include <cuda_runtime.h>
#include <math.h>
#include <stdint.h>

#define Bdim  4096
#define Fdim  4096
#define Vdim  1024
#define Edim  512
#define Hdim  1024
#define Ldim  30
#define LP1   (Ldim + 1)
#define BOUNDT 1023
#define G4H   (4 * Hdim)

// ================= scratch (static device globals) =================
__device__ float g_Ts[(size_t)Vdim * G4H];      // sender table [V][g*H + j] (biases folded)
__device__ float g_Tr[(size_t)Vdim * G4H];      // receiver table, same layout
__device__ float g_gates[(size_t)Bdim * G4H];   // per-step gate tensor (L2-resident)
__device__ float g_hA[(size_t)Bdim * Hdim];
__device__ float g_hB[(size_t)Bdim * Hdim];
__device__ float g_c [(size_t)Bdim * Hdim];
__device__ float g_scores[(size_t)Bdim * Vdim];
__device__ float g_r[(size_t)Bdim * Fdim];
__device__ float g_nwc[Vdim];
__device__ float g_vl[Bdim];
__device__ int   g_tok[Bdim];
__device__ int   g_sl[Bdim];
__device__ int   g_m[(size_t)Bdim * LP1];
__device__ int   g_wcnt[Vdim];
__device__ float g_loss_sum;
__device__ float g_acc_sum;

__device__ __forceinline__ float sigf(float x) {
    if (x >= 0.f) return 1.f / (1.f + expf(-x));
    float e = expf(x);
    return e / (1.f + e);
}

// ================= small kernels =================
__global__ void init_kernel() {
    int idx = blockIdx.x * blockDim.x + threadIdx.x;
    if (idx < Bdim * Hdim) g_c[idx] = 0.f;
    if (idx < Bdim) {
        g_tok[idx] = BOUNDT; g_sl[idx] = LP1; g_vl[idx] = 0.f;
        g_m[(size_t)idx * LP1] = BOUNDT;
    }
    if (idx < Vdim) g_wcnt[idx] = 0;
    if (idx == 0) { g_loss_sum = 0.f; g_acc_sum = 0.f; }
}

__global__ void zero_hc_kernel() {
    int idx = blockIdx.x * blockDim.x + threadIdx.x;
    if (idx < Bdim * Hdim) { g_hA[idx] = 0.f; g_c[idx] = 0.f; }
}

__global__ void nwc_kernel(const float* __restrict__ wc) {
    __shared__ float red[1024];
    int t = threadIdx.x;
    float v = wc[t];
    if (t == BOUNDT) v *= 0.1f;
    red[t] = v;
    __syncthreads();
    for (int s = 512; s > 0; s >>= 1) {
        if (t < s) red[t] += red[t + s];
        __syncthreads();
    }
    float denom = red[0];
    g_nwc[t] = (denom > 0.f) ? v / denom : v;
}

// ================= fp32 SGEMM (R1-exact; DO NOT CHANGE ARITHMETIC) =================
__global__ __launch_bounds__(256)
void sgemm_nt(const float* __restrict__ A, const float* __restrict__ Bm,
              const float* __restrict__ bias1, const float* __restrict__ bias2,
              float* __restrict__ C, int M, int N, int K) {
    __shared__ __align__(16) float As[16][64];
    __shared__ __align__(16) float Bs[16][64];
    int tid = threadIdx.x;
    int tx = tid & 15, ty = tid >> 4;
    int m0 = blockIdx.y * 64, n0 = blockIdx.x * 64;
    int lrow = tid >> 2, lcol = (tid & 3) * 4;
    float acc[4][4] = {};
    for (int k0 = 0; k0 < K; k0 += 16) {
        float4 av = *(const float4*)(A + (size_t)(m0 + lrow) * K + k0 + lcol);
        float4 bv = *(const float4*)(Bm + (size_t)(n0 + lrow) * K + k0 + lcol);
        As[lcol + 0][lrow] = av.x; As[lcol + 1][lrow] = av.y;
        As[lcol + 2][lrow] = av.z; As[lcol + 3][lrow] = av.w;
        Bs[lcol + 0][lrow] = bv.x; Bs[lcol + 1][lrow] = bv.y;
        Bs[lcol + 2][lrow] = bv.z; Bs[lcol + 3][lrow] = bv.w;
        __syncthreads();
#pragma unroll
        for (int k = 0; k < 16; k++) {
            float4 a = *(const float4*)&As[k][ty << 2];
            float4 b = *(const float4*)&Bs[k][tx << 2];
            float ar[4] = {a.x, a.y, a.z, a.w};
            float br[4] = {b.x, b.y, b.z, b.w};
#pragma unroll
            for (int i = 0; i < 4; i++)
#pragma unroll
                for (int j = 0; j < 4; j++) acc[i][j] += ar[i] * br[j];
        }
        __syncthreads();
    }
    float bb[4];
#pragma unroll
    for (int j = 0; j < 4; j++) {
        int n = n0 + (tx << 2) + j;
        bb[j] = (bias1 ? bias1[n] : 0.f) + (bias2 ? bias2[n] : 0.f);
    }
#pragma unroll
    for (int i = 0; i < 4; i++) {
        float4 o = make_float4(acc[i][0] + bb[0], acc[i][1] + bb[1],
                               acc[i][2] + bb[2], acc[i][3] + bb[3]);
        *(float4*)(C + (size_t)(m0 + (ty << 2) + i) * N + n0 + (tx << 2)) = o;
    }
}

// ================= seeded SGEMM: C = T[tok] + A @ B^T =================
// Identical tiling/inner loop to sgemm_nt; accumulators are initialized from
// the gathered table row instead of 0. Per-output FFMA chain (seed, then
// k = 0..K-1 ascending, one FFMA per k) is bit-identical to the fused
// lstm_step of R1/R10.
__global__ __launch_bounds__(256)
void sgemm_seed(const float* __restrict__ A, const float* __restrict__ Bm,
                const float* __restrict__ T,      // [V, N] seed table
                const int* __restrict__ tok, int tok_stride,
                float* __restrict__ C, int M, int N, int K) {
    __shared__ __align__(16) float As[16][64];
    __shared__ __align__(16) float Bs[16][64];
    int tid = threadIdx.x;
    int tx = tid & 15, ty = tid >> 4;
    int m0 = blockIdx.y * 64, n0 = blockIdx.x * 64;
    int lrow = tid >> 2, lcol = (tid & 3) * 4;

    float acc[4][4];
#pragma unroll
    for (int i = 0; i < 4; i++) {
        int row = m0 + (ty << 2) + i;
        int t_r = tok[(size_t)row * tok_stride];
        float4 v = *(const float4*)(T + (size_t)t_r * N + n0 + (tx << 2));
        acc[i][0] = v.x; acc[i][1] = v.y; acc[i][2] = v.z; acc[i][3] = v.w;
    }

    for (int k0 = 0; k0 < K; k0 += 16) {
        float4 av = *(const float4*)(A + (size_t)(m0 + lrow) * K + k0 + lcol);
        float4 bv = *(const float4*)(Bm + (size_t)(n0 + lrow) * K + k0 + lcol);
        As[lcol + 0][lrow] = av.x; As[lcol + 1][lrow] = av.y;
        As[lcol + 2][lrow] = av.z; As[lcol + 3][lrow] = av.w;
        Bs[lcol + 0][lrow] = bv.x; Bs[lcol + 1][lrow] = bv.y;
        Bs[lcol + 2][lrow] = bv.z; Bs[lcol + 3][lrow] = bv.w;
        __syncthreads();
#pragma unroll
        for (int k = 0; k < 16; k++) {
            float4 a = *(const float4*)&As[k][ty << 2];
            float4 b = *(const float4*)&Bs[k][tx << 2];
            float ar[4] = {a.x, a.y, a.z, a.w};
            float br[4] = {b.x, b.y, b.z, b.w};
#pragma unroll
            for (int i = 0; i < 4; i++)
#pragma unroll
                for (int j = 0; j < 4; j++) acc[i][j] += ar[i] * br[j];
        }
        __syncthreads();
    }
#pragma unroll
    for (int i = 0; i < 4; i++) {
        float4 o = make_float4(acc[i][0], acc[i][1], acc[i][2], acc[i][3]);
        *(float4*)(C + (size_t)(m0 + (ty << 2) + i) * N + n0 + (tx << 2)) = o;
    }
}

// ================= elementwise LSTM cell (same expression as R1 epilogue) =================
__global__ __launch_bounds__(256)
void lstm_cell(const float* __restrict__ gates, float* __restrict__ c_io,
               float* __restrict__ h_out) {
    int idx4 = blockIdx.x * blockDim.x + threadIdx.x;   // one float4 per thread
    if (idx4 >= Bdim * Hdim / 4) return;
    int row = idx4 / (Hdim / 4);
    int j4  = (idx4 % (Hdim / 4)) * 4;
    const float* grow = gates + (size_t)row * G4H;
    float4 iv = *(const float4*)(grow + 0 * Hdim + j4);
    float4 fv = *(const float4*)(grow + 1 * Hdim + j4);
    float4 gv = *(const float4*)(grow + 2 * Hdim + j4);
    float4 ov = *(const float4*)(grow + 3 * Hdim + j4);
    size_t off = (size_t)row * Hdim + j4;
    float4 co = *(const float4*)(c_io + off);
    float4 cn, hn;
    {
        float c0 = sigf(fv.x) * co.x + sigf(iv.x) * tanhf(gv.x);
        float c1 = sigf(fv.y) * co.y + sigf(iv.y) * tanhf(gv.y);
        float c2 = sigf(fv.z) * co.z + sigf(iv.z) * tanhf(gv.z);
        float c3 = sigf(fv.w) * co.w + sigf(iv.w) * tanhf(gv.w);
        cn = make_float4(c0, c1, c2, c3);
        hn = make_float4(sigf(ov.x) * tanhf(c0), sigf(ov.y) * tanhf(c1),
                         sigf(ov.z) * tanhf(c2), sigf(ov.w) * tanhf(c3));
    }
    *(float4*)(c_io + off) = cn;
    *(float4*)(h_out + off) = hn;
}

// ================= R1-exact argmax + CE reduce =================
__global__ void score_reduce(const float* __restrict__ scores, int step) {
    int gwarp = (blockIdx.x * blockDim.x + threadIdx.x) >> 5;
    int lane = threadIdx.x & 31;
    if (gwarp >= Bdim) return;
    const float* srow = scores + (size_t)gwarp * Vdim;

    float lvals[32];
    float best = -INFINITY; int bidx = 0;
    float lmax = -INFINITY;
#pragma unroll
    for (int j = 0; j < 32; j++) {
        int idx = lane + j * 32;
        float s = srow[idx];
        float l = s - g_nwc[idx];
        lvals[j] = l;
        if (s > best) { best = s; bidx = idx; }
        lmax = fmaxf(lmax, l);
    }
#pragma unroll
    for (int off = 16; off; off >>= 1) {
        float ov = __shfl_down_sync(0xffffffffu, best, off);
        int   oi = __shfl_down_sync(0xffffffffu, bidx, off);
        if (ov > best || (ov == best && oi < bidx)) { best = ov; bidx = oi; }
        lmax = fmaxf(lmax, __shfl_down_sync(0xffffffffu, lmax, off));
    }
    bidx = __shfl_sync(0xffffffffu, bidx, 0);
    lmax = __shfl_sync(0xffffffffu, lmax, 0);

    float se = 0.f;
#pragma unroll
    for (int j = 0; j < 32; j++) se += expf(lvals[j] - lmax);
#pragma unroll
    for (int off = 16; off; off >>= 1) se += __shfl_down_sync(0xffffffffu, se, off);

    if (lane == 0) {
        float l_tok = srow[bidx] - g_nwc[bidx];
        float ce = logf(se) + lmax - l_tok;
        g_m[(size_t)gwarp * LP1 + step + 1] = bidx;
        g_tok[gwarp] = bidx;
        if (bidx == BOUNDT && g_sl[gwarp] == LP1) g_sl[gwarp] = step + 2;
        g_vl[gwarp] += ce;
    }
}

__global__ void pad_kernel() {
    int idx = blockIdx.x * blockDim.x + threadIdx.x;
    if (idx >= Bdim * LP1) return;
    int b = idx / LP1, p = idx % LP1;
    if (p >= g_sl[b]) g_m[idx] = BOUNDT;
}

__global__ void hist_kernel() {
    __shared__ int hs[Vdim];
    for (int i = threadIdx.x; i < Vdim; i += blockDim.x) hs[i] = 0;
    __syncthreads();
    int total = Bdim * LP1;
    for (int idx = blockIdx.x * blockDim.x + threadIdx.x; idx < total;
         idx += gridDim.x * blockDim.x)
        atomicAdd(&hs[g_m[idx]], 1);
    __syncthreads();
    for (int i = threadIdx.x; i < Vdim; i += blockDim.x)
        if (hs[i]) atomicAdd(&g_wcnt[i], hs[i]);
}

__global__ void final_score(const float* __restrict__ target,
                            const float* __restrict__ dis) {
    int b = blockIdx.x;
    int t = threadIdx.x;
    const float* rrow = g_r + (size_t)b * Fdim;
    const float* trow = target + (size_t)b * Fdim;
    const float* d0 = dis + (size_t)b * Fdim;
    const float* d1 = dis + (size_t)Bdim * Fdim + (size_t)b * Fdim;
    const float* d2 = dis + (size_t)2 * Bdim * Fdim + (size_t)b * Fdim;
    float a0 = 0.f, a1 = 0.f, a2 = 0.f, a3 = 0.f;
    for (int f = t; f < Fdim; f += 256) {
        float rv = rrow[f];
        a0 += trow[f] * rv; a1 += d0[f] * rv; a2 += d1[f] * rv; a3 += d2[f] * rv;
    }
    __shared__ float sh[4][256];
    sh[0][t] = a0; sh[1][t] = a1; sh[2][t] = a2; sh[3][t] = a3;
    __syncthreads();
    for (int s = 128; s > 0; s >>= 1) {
        if (t < s) {
            sh[0][t] += sh[0][t + s]; sh[1][t] += sh[1][t + s];
            sh[2][t] += sh[2][t + s]; sh[3][t] += sh[3][t + s];
        }
        __syncthreads();
    }
    if (t == 0) {
        float ts = sh[0][0], s1 = sh[1][0], s2 = sh[2][0], s3 = sh[3][0];
        float loss = fmaxf(0.f, 1.f - ts + s1) + fmaxf(0.f, 1.f - ts + s2) +
                     fmaxf(0.f, 1.f - ts + s3) + 0.1f * g_vl[b];
        float es = expf(ts), e1 = expf(s1), e2 = expf(s2), e3 = expf(s3);
        float acc = (es >= e1 && es >= e2 && es >= e3) ? 1.f : 0.f;
        atomicAdd(&g_loss_sum, loss);
        atomicAdd(&g_acc_sum, acc);
    }
}

__global__ void emit_kernel(float* __restrict__ out, int out_size) {
    int idx = blockIdx.x * blockDim.x + threadIdx.x;
    if (idx >= out_size) return;
    const int M_OFF = 2;
    const int WC_OFF = 2 + Bdim * LP1;
    const int TOTAL = WC_OFF + Vdim;
    if (idx == 0)            out[0] = g_loss_sum / (float)Bdim;
    else if (idx == 1)       out[1] = g_acc_sum / (float)Bdim;
    else if (idx < WC_OFF)   out[idx] = (float)g_m[idx - M_OFF];
    else if (idx < TOTAL)    out[idx] = (float)g_wcnt[idx - WC_OFF];
    else                     out[idx] = 0.f;
}

// ================= host launcher =================
extern "C" void kernel_launch(void* const* d_in, const int* in_sizes, int n_in,
                              void* d_out, int out_size) {
    const float* target    = (const float*)d_in[0];
    const float* dis       = (const float*)d_in[1];
    const float* wcounts   = (const float*)d_in[2];
    const float* emb_s     = (const float*)d_in[3];
    const float* aff_s_W   = (const float*)d_in[4];
    const float* aff_s_b   = (const float*)d_in[5];
    const float* lstm_Wih  = (const float*)d_in[6];
    const float* lstm_Whh  = (const float*)d_in[7];
    const float* lstm_bih  = (const float*)d_in[8];
    const float* lstm_bhh  = (const float*)d_in[9];
    const float* lp_W      = (const float*)d_in[10];
    const float* lp_b      = (const float*)d_in[11];
    const float* emb_r     = (const float*)d_in[12];
    const float* rlstm_Wih = (const float*)d_in[13];
    const float* rlstm_Whh = (const float*)d_in[14];
    const float* rlstm_bih = (const float*)d_in[15];
    const float* rlstm_bhh = (const float*)d_in[16];
    const float* aff_r_W   = (const float*)d_in[17];
    const float* aff_r_b   = (const float*)d_in[18];

    float *Ts, *Tr, *gates, *hA, *hB, *cc, *sc, *rr;
    int *mm, *tk;
    cudaGetSymbolAddress((void**)&Ts, g_Ts);
    cudaGetSymbolAddress((void**)&Tr, g_Tr);
    cudaGetSymbolAddress((void**)&gates, g_gates);
    cudaGetSymbolAddress((void**)&hA, g_hA);
    cudaGetSymbolAddress((void**)&hB, g_hB);
    cudaGetSymbolAddress((void**)&cc, g_c);
    cudaGetSymbolAddress((void**)&sc, g_scores);
    cudaGetSymbolAddress((void**)&rr, g_r);
    cudaGetSymbolAddress((void**)&mm, g_m);
    cudaGetSymbolAddress((void**)&tk, g_tok);

    init_kernel<<<(Bdim * Hdim + 255) / 256, 256>>>();
    nwc_kernel<<<1, 1024>>>(wcounts);

    // x-projection tables (biases folded), fp32 — native [V][g*H+j] layout
    sgemm_nt<<<dim3(G4H / 64, Vdim / 64), 256>>>(emb_s, lstm_Wih, lstm_bih, lstm_bhh,
                                                 Ts, Vdim, G4H, Edim);
    sgemm_nt<<<dim3(G4H / 64, Vdim / 64), 256>>>(emb_r, rlstm_Wih, rlstm_bih, rlstm_bhh,
                                                 Tr, Vdim, G4H, Edim);

    // h0 = target @ aff_s_W^T + b
    sgemm_nt<<<dim3(Hdim / 64, Bdim / 64), 256>>>(target, aff_s_W, aff_s_b, nullptr,
                                                  hA, Bdim, Hdim, Fdim);

    const dim3 gridGate(G4H / 64, Bdim / 64);   // 64 x 64 blocks
    const int  cellBlocks = (Bdim * Hdim / 4 + 255) / 256;

    // ---- sender: 30 greedy steps (bit-identical decision arithmetic) ----
    for (int i = 0; i < Ldim; i++) {
        float* hin  = (i & 1) ? hB : hA;
        float* hout = (i & 1) ? hA : hB;
        sgemm_seed<<<gridGate, 256>>>(hin, lstm_Whh, Ts, tk, 1, gates,
                                      Bdim, G4H, Hdim);
        lstm_cell<<<cellBlocks, 256>>>(gates, cc, hout);
        sgemm_nt<<<dim3(Vdim / 64, Bdim / 64), 256>>>(hout, lp_W, lp_b, nullptr,
                                                      sc, Bdim, Vdim, Hdim);
        score_reduce<<<Bdim / 4, 128>>>(sc, i);
    }

    pad_kernel<<<(Bdim * LP1 + 255) / 256, 256>>>();
    hist_kernel<<<128, 256>>>();

    // ---- receiver: 31 steps, same split kernels ----
    zero_hc_kernel<<<(Bdim * Hdim + 255) / 256, 256>>>();
    for (int t = 0; t < LP1; t++) {
        float* hin  = (t & 1) ? hB : hA;
        float* hout = (t & 1) ? hA : hB;
        sgemm_seed<<<gridGate, 256>>>(hin, rlstm_Whh, Tr, mm + t, LP1, gates,
                                      Bdim, G4H, Hdim);
        lstm_cell<<<cellBlocks, 256>>>(gates, cc, hout);
    }

    // r = h_final @ aff_r_W^T + b  (t=30 even -> final h in hB)
    sgemm_nt<<<dim3(Fdim / 64, Bdim / 64), 256>>>(hB, aff_r_W, aff_r_b, nullptr,
                                                  rr, Bdim, Fdim, Hdim);

    final_score<<<Bdim, 256>>>(target, dis);

    int total = 2 + Bdim * LP1 + Vdim;
    int n_emit = out_size > total ? out_size : total;
    emit_kernel<<<(n_emit + 255) / 256, 256>>>((float*)d_out, out_size);
}